// round 5
// baseline (speedup 1.0000x reference)
#include <cuda_runtime.h>
#include <math.h>

#define NMAX 50000
#define EMAX 400000

// ---------------- scratch (device globals; no allocs allowed) ----------------
__device__ float g_hs [NMAX*64];   // lin1 scalar features (gather source)
__device__ float g_hv [NMAX*96];   // lin1 vector features [n][u*3+i], u<32
__device__ float g_scs[NMAX*96];   // skip scalar (stride OS per layer)
__device__ float g_scv[NMAX*96];   // skip vector [n][k*3+i]
__device__ float g_Ms [NMAX*96];   // scalar message sums
__device__ float g_Mv [NMAX*288];  // vector message sums, PLANE-MAJOR [n][i*96+u]
__device__ float g_s1 [NMAX*96];   // layer1 scalar output
__device__ float g_v1 [NMAX*96];   // layer1 vector output
__device__ float g_deg[NMAX];
__device__ float g_w  [(size_t)EMAX*192];   // per-edge MLP weights (materialized)

// CSR (built once, shared by both layers)
__device__ int g_cnt   [NMAX];
__device__ int g_cur   [NMAX];
__device__ int g_rowptr[NMAX+1];
__device__ int g_eid   [EMAX];

__device__ __forceinline__ float siluf(float x)   { return x / (1.f + __expf(-x)); }
__device__ __forceinline__ float sigmf(float x)   { return 1.f / (1.f + __expf(-x)); }

#define INV_S10 0.31622776601683794f
#define INV_S32 0.17677669529663687f
#define INV_S96 0.10206207261596575f
#define INV_S3  0.57735026918962576f

// ---- packed f32x2 helpers ----
__device__ __forceinline__ unsigned long long pack2(float lo, float hi) {
    unsigned long long r;
    asm("mov.b64 %0, {%1, %2};" : "=l"(r) : "f"(lo), "f"(hi));
    return r;
}
__device__ __forceinline__ void fma2(unsigned long long &d,
                                     unsigned long long a, unsigned long long b) {
    asm("fma.rn.f32x2 %0, %1, %2, %0;" : "+l"(d) : "l"(a), "l"(b));
}
__device__ __forceinline__ float2 unpack2(unsigned long long v) {
    float2 r;
    asm("mov.b64 {%0, %1}, %2;" : "=f"(r.x), "=f"(r.y) : "l"(v));
    return r;
}

// ---------------- CSR build ----------------
__global__ void k_cnt_zero(int N)
{
    int i = blockIdx.x * blockDim.x + threadIdx.x;
    int stride = gridDim.x * blockDim.x;
    for (int j = i; j < N; j += stride) g_cnt[j] = 0;
}

__global__ void k_count(const int* __restrict__ dst, int E)
{
    int i = blockIdx.x * blockDim.x + threadIdx.x;
    if (i < E) atomicAdd(&g_cnt[dst[i]], 1);
}

__global__ void k_scan(int N)   // single block, 1024 threads
{
    __shared__ int part[1024];
    int t = threadIdx.x;
    int chunk = (N + 1023) >> 10;
    int b = t * chunk, e2 = min(b + chunk, N);
    int s = 0;
    for (int i = b; i < e2; i++) s += g_cnt[i];
    part[t] = s;
    __syncthreads();
    for (int off = 1; off < 1024; off <<= 1) {
        int v = (t >= off) ? part[t - off] : 0;
        __syncthreads();
        part[t] += v;
        __syncthreads();
    }
    int base = (t == 0) ? 0 : part[t - 1];
    for (int i = b; i < e2; i++) {
        int c = g_cnt[i];
        g_rowptr[i] = base;
        g_cur[i]    = base;
        g_deg[i]    = (float)max(c, 1);
        base += c;
    }
    if (t == 0) g_rowptr[N] = part[1023];
}

__global__ void k_fill(const int* __restrict__ dst, int E)
{
    int i = blockIdx.x * blockDim.x + threadIdx.x;
    if (i < E) {
        int p = atomicAdd(&g_cur[dst[i]], 1);
        g_eid[p] = i;
    }
}

// ---------------- node prep: hs/hv + skip connections ----------------
template<int OS, bool L2IN>
__global__ __launch_bounds__(256) void k_nodeprep(
    const float* __restrict__ ns_in, const float* __restrict__ nv_in,
    const float* __restrict__ attr,
    const float* __restrict__ Wl1s, const float* __restrict__ Wl1v,
    const float* __restrict__ Wscs, const float* __restrict__ Wscv, int N)
{
    constexpr int WT = 64 + OS;
    extern __shared__ float sm[];
    float* sA  = sm;                 // [64][65]
    float* sV  = sA + 64*65;         // [3][64][33]
    float* sWs = sV + 3*64*33;       // [64][WT]
    float* sWv = sWs + 64*WT;        // [32][64]
    float* sAt = sWv + 32*64;        // [64]
    int t  = threadIdx.x;
    int n0 = blockIdx.x * 64;

    for (int idx = t; idx < 64*WT; idx += 256) {
        int u = idx / WT, o = idx - u*WT;
        sWs[idx] = (o < 64) ? Wl1s[u*64 + o] : Wscs[u*OS + (o-64)];
    }
    for (int idx = t; idx < 2048; idx += 256) {
        int u = idx >> 6, o = idx & 63;
        sWv[idx] = (o < 32) ? Wl1v[u*32 + o] : Wscv[u*32 + (o-32)];
    }
    for (int idx = t; idx < 4096; idx += 256) {
        int ln = idx >> 6, u = idx & 63;
        int n = n0 + ln; float v = 0.f;
        if (n < N) v = L2IN ? siluf(g_s1[n*96 + u]) : ns_in[n*64 + u];
        sA[ln*65 + u] = v;
    }
    for (int idx = t; idx < 2048; idx += 256) {
        int ln = idx >> 5, u = idx & 31;
        int n = n0 + ln;
        float a0 = 0.f, a1 = 0.f, a2 = 0.f;
        if (n < N) {
            if (L2IN) {
                float g = sigmf(g_s1[n*96 + 64 + u]);
                a0 = g_v1[n*96 + u*3+0] * g;
                a1 = g_v1[n*96 + u*3+1] * g;
                a2 = g_v1[n*96 + u*3+2] * g;
            } else {
                a0 = nv_in[(n*32+u)*3+0];
                a1 = nv_in[(n*32+u)*3+1];
                a2 = nv_in[(n*32+u)*3+2];
            }
        }
        sV[(0*64+ln)*33 + u] = a0;
        sV[(1*64+ln)*33 + u] = a1;
        sV[(2*64+ln)*33 + u] = a2;
    }
    if (t < 64) { int n = n0 + t; sAt[t] = (n < N) ? attr[n] : 0.f; }
    __syncthreads();

    constexpr int CG = WT / 4;
    for (int tid = t; tid < 16*CG; tid += 256) {
        int cg = tid % CG, ng = tid / CG;
        float acc[4][4];
        #pragma unroll
        for (int j = 0; j < 4; j++) { acc[j][0]=0;acc[j][1]=0;acc[j][2]=0;acc[j][3]=0; }
        #pragma unroll 8
        for (int k = 0; k < 64; k++) {
            float b0 = sWs[k*WT + cg*4 + 0];
            float b1 = sWs[k*WT + cg*4 + 1];
            float b2 = sWs[k*WT + cg*4 + 2];
            float b3 = sWs[k*WT + cg*4 + 3];
            #pragma unroll
            for (int j = 0; j < 4; j++) {
                float a = sA[(ng*4+j)*65 + k];
                acc[j][0] += a*b0; acc[j][1] += a*b1; acc[j][2] += a*b2; acc[j][3] += a*b3;
            }
        }
        #pragma unroll
        for (int j = 0; j < 4; j++) {
            int n = n0 + ng*4 + j;
            if (n >= N) continue;
            float f = sAt[ng*4+j] * 0.125f;
            #pragma unroll
            for (int m = 0; m < 4; m++) {
                int o = cg*4 + m;
                float v = acc[j][m] * f;
                if (o < 64) g_hs[n*64 + o] = v;
                else        g_scs[n*OS + (o-64)] = v;
            }
        }
    }

    {
        int cg = t & 15, ng = t >> 4;
        #pragma unroll
        for (int i = 0; i < 3; i++) {
            float acc[4][4];
            #pragma unroll
            for (int j = 0; j < 4; j++) { acc[j][0]=0;acc[j][1]=0;acc[j][2]=0;acc[j][3]=0; }
            #pragma unroll 8
            for (int k = 0; k < 32; k++) {
                float b0 = sWv[k*64 + cg*4 + 0];
                float b1 = sWv[k*64 + cg*4 + 1];
                float b2 = sWv[k*64 + cg*4 + 2];
                float b3 = sWv[k*64 + cg*4 + 3];
                #pragma unroll
                for (int j = 0; j < 4; j++) {
                    float a = sV[(i*64 + ng*4+j)*33 + k];
                    acc[j][0] += a*b0; acc[j][1] += a*b1; acc[j][2] += a*b2; acc[j][3] += a*b3;
                }
            }
            #pragma unroll
            for (int j = 0; j < 4; j++) {
                int n = n0 + ng*4 + j;
                if (n >= N) continue;
                float f = sAt[ng*4+j] * INV_S32;
                #pragma unroll
                for (int m = 0; m < 4; m++) {
                    int o = cg*4 + m;
                    float v = acc[j][m] * f;
                    if (o < 32) g_hv [n*96 + o*3 + i]      = v;
                    else        g_scv[n*96 + (o-32)*3 + i] = v;
                }
            }
        }
    }
}

// ---------------- edge-MLP kernel: w = silu(esc@W1/√10)@W2/8 -> g_w ----------------
__global__ __launch_bounds__(384, 2) void k_w(
    const float* __restrict__ esc,
    const float* __restrict__ Wfc1, const float* __restrict__ Wfc2, int E)
{
    extern __shared__ float sm[];
    float* s_W1  = sm;               // [10][64]
    float* s_esc = s_W1 + 640;       // [64][10]
    float* s_h   = s_esc + 640;      // [64 k][64 e]  (transposed)
    float* s_w   = s_h + 4096;       // [64 e][192]
    int t  = threadIdx.x;
    int e0 = blockIdx.x * 64;
    int nE = min(64, E - e0);

    for (int idx = t; idx < 640; idx += 384) s_W1[idx] = Wfc1[idx];
    for (int idx = t; idx < 640; idx += 384)
        s_esc[idx] = (idx < nE*10) ? esc[(long)e0*10 + idx] : 0.f;
    __syncthreads();

    // phase 1: h store transposed s_h[o][e]
    for (int idx = t; idx < 4096; idx += 384) {
        int e = idx & 63, o = idx >> 6;
        float a = 0.f;
        #pragma unroll
        for (int j = 0; j < 10; j++) a += s_esc[e*10 + j] * s_W1[j*64 + o];
        s_h[o*64 + e] = siluf(a * INV_S10);
    }
    __syncthreads();

    // phase 2: (64 edges x 192) pair-packed f32x2 FMA
    {
        int cg = t % 48;
        int eg = t / 48;   // 0..7
        unsigned long long acc[4][4];
        #pragma unroll
        for (int p = 0; p < 4; p++)
            #pragma unroll
            for (int c = 0; c < 4; c++) acc[p][c] = 0ull;
        const float4* W2 = reinterpret_cast<const float4*>(Wfc2) + cg;
        #pragma unroll 4
        for (int k = 0; k < 64; k++) {
            float4 b = __ldg(W2 + k*48);
            unsigned long long b2[4];
            b2[0] = pack2(b.x, b.x); b2[1] = pack2(b.y, b.y);
            b2[2] = pack2(b.z, b.z); b2[3] = pack2(b.w, b.w);
            const unsigned long long* hp =
                reinterpret_cast<const unsigned long long*>(s_h + k*64 + eg*8);
            ulonglong2 hA = *reinterpret_cast<const ulonglong2*>(hp);
            ulonglong2 hB = *reinterpret_cast<const ulonglong2*>(hp + 2);
            unsigned long long h2[4] = {hA.x, hA.y, hB.x, hB.y};
            #pragma unroll
            for (int p = 0; p < 4; p++) {
                fma2(acc[p][0], h2[p], b2[0]);
                fma2(acc[p][1], h2[p], b2[1]);
                fma2(acc[p][2], h2[p], b2[2]);
                fma2(acc[p][3], h2[p], b2[3]);
            }
        }
        #pragma unroll
        for (int p = 0; p < 4; p++) {
            float* w0 = s_w + (eg*8 + 2*p)     * 192 + cg*4;
            float* w1 = s_w + (eg*8 + 2*p + 1) * 192 + cg*4;
            #pragma unroll
            for (int c = 0; c < 4; c++) {
                float2 v = unpack2(acc[p][c]);
                w0[c] = v.x * 0.125f;
                w1[c] = v.y * 0.125f;
            }
        }
    }
    __syncthreads();

    // write out (coalesced float4)
    int lim = nE * 48;
    float4* dst4 = reinterpret_cast<float4*>(g_w + (size_t)e0 * 192);
    const float4* src4 = reinterpret_cast<const float4*>(s_w);
    for (int idx = t; idx < lim; idx += 384) dst4[idx] = src4[idx];
}

// ---------------- aggregation: warp per dst, CSR order, no atomics ----------------
__global__ __launch_bounds__(256) void k_agg(
    const float* __restrict__ sh, const int* __restrict__ src, int N)
{
    int lane = threadIdx.x & 31;
    int wid  = (blockIdx.x * (blockDim.x >> 5)) + (threadIdx.x >> 5);
    int wstep = gridDim.x * (blockDim.x >> 5);

    for (int d = wid; d < N; d += wstep) {
        int beg = __ldg(&g_rowptr[d]);
        int end = __ldg(&g_rowptr[d+1]);

        float as0 = 0.f, as1 = 0.f, as2 = 0.f;
        float av00=0.f, av01=0.f, av02=0.f;
        float av10=0.f, av11=0.f, av12=0.f;
        float av20=0.f, av21=0.f, av22=0.f;

        int e_next = (beg < end) ? __ldg(&g_eid[beg]) : 0;
        for (int j = beg; j < end; j++) {
            int e = e_next;
            if (j + 1 < end) e_next = __ldg(&g_eid[j+1]);
            int s = __ldg(&src[e]);
            float4 sh4 = __ldg(reinterpret_cast<const float4*>(sh) + e);
            float sh0 = sh4.x, shx = sh4.y, shy = sh4.z, shz = sh4.w;

            const float* wr = g_w + (size_t)e * 192;
            float w1a = __ldg(wr + lane);
            float w1b = __ldg(wr + 32 + lane);
            float w2a = __ldg(wr + 64 + lane);
            float w2b = __ldg(wr + 96 + lane);
            float w3  = __ldg(wr + 128 + lane);
            float w4  = __ldg(wr + 160 + lane);

            const float* hsp = g_hs + (size_t)s * 64;
            float gs0 = __ldg(hsp + lane);
            float gs1 = __ldg(hsp + 32 + lane);
            const float* hvp = g_hv + (size_t)s * 96 + lane*3;
            float gv0 = __ldg(hvp + 0);
            float gv1 = __ldg(hvp + 1);
            float gv2 = __ldg(hvp + 2);

            // Ms
            as0 += gs0 * sh0 * w1a;
            as1 += gs1 * sh0 * w1b;
            as2 += (gv0*shx + gv1*shy + gv2*shz) * INV_S3 * w4;
            // Mv  (plane-major; lane owns u = lane, lane+32, lane+64)
            float p0 = gs0 * w2a, p1 = gs1 * w2b, g3 = sh0 * w3;
            av00 += p0 * shx;  av01 += p1 * shx;  av02 += gv0 * g3;
            av10 += p0 * shy;  av11 += p1 * shy;  av12 += gv1 * g3;
            av20 += p0 * shz;  av21 += p1 * shz;  av22 += gv2 * g3;
        }

        float* Msd = g_Ms + (size_t)d * 96;
        Msd[lane]      = as0;
        Msd[32 + lane] = as1;
        Msd[64 + lane] = as2;
        float* Mvd = g_Mv + (size_t)d * 288;
        Mvd[          lane] = av00; Mvd[ 32 + lane] = av01; Mvd[ 64 + lane] = av02;
        Mvd[ 96     + lane] = av10; Mvd[128 + lane] = av11; Mvd[160 + lane] = av12;
        Mvd[192     + lane] = av20; Mvd[224 + lane] = av21; Mvd[256 + lane] = av22;
    }
}

// ---------------- node finalize: mean, alpha, lin2, skip add ----------------
template<int OS, bool LAST>
__global__ __launch_bounds__(256) void k_nodefinal(
    const float* __restrict__ attr,
    const float* __restrict__ Wl2s,   // [96][OS]
    const float* __restrict__ Wl2v,   // [96][32]
    const float* __restrict__ Wa,     // [96]
    float* __restrict__ out, int N)
{
    extern __shared__ float sm[];
    float* sMs = sm;                  // [64][97]
    float* sMv = sMs + 64*97;         // [64][97]
    float* sWs = sMv + 64*97;         // [96][OS]
    float* sWv = sWs + 96*OS;         // [96][32]
    float* sWa = sWv + 96*32;         // [96]
    float* sAl = sWa + 96;            // [64]
    float* sIv = sAl + 64;            // [64]
    float* sAt = sIv + 64;            // [64]
    int t  = threadIdx.x;
    int n0 = blockIdx.x * 64;

    for (int idx = t; idx < 96*OS; idx += 256) sWs[idx] = Wl2s[idx];
    for (int idx = t; idx < 96*32; idx += 256) sWv[idx] = Wl2v[idx];
    if (t < 96) sWa[t] = Wa[t];
    if (t < 64) {
        int n = n0 + t;
        sIv[t] = (n < N) ? 1.f / fmaxf(g_deg[n], 1.f) : 0.f;
        sAt[t] = (n < N) ? attr[n] : 0.f;
    }
    __syncthreads();
    for (int idx = t; idx < 64*96; idx += 256) {
        int ln = idx / 96, j = idx - ln*96;
        int n = n0 + ln;
        sMs[ln*97 + j] = (n < N) ? g_Ms[n*96 + j] * sIv[ln] : 0.f;
    }
    __syncthreads();
    if (t < 64) {
        float a = 0.f;
        #pragma unroll 8
        for (int j = 0; j < 96; j++) a += sMs[t*97 + j] * sWa[j];
        sAl[t] = a * INV_S96 * sAt[t];
    }
    __syncthreads();

    constexpr int CG = OS / 4;
    for (int tid = t; tid < 16*CG; tid += 256) {
        int cg = tid % CG, ng = tid / CG;
        float acc[4][4];
        #pragma unroll
        for (int j = 0; j < 4; j++) { acc[j][0]=0;acc[j][1]=0;acc[j][2]=0;acc[j][3]=0; }
        #pragma unroll 8
        for (int k = 0; k < 96; k++) {
            float b0 = sWs[k*OS + cg*4 + 0];
            float b1 = sWs[k*OS + cg*4 + 1];
            float b2 = sWs[k*OS + cg*4 + 2];
            float b3 = sWs[k*OS + cg*4 + 3];
            #pragma unroll
            for (int j = 0; j < 4; j++) {
                float a = sMs[(ng*4+j)*97 + k];
                acc[j][0] += a*b0; acc[j][1] += a*b1; acc[j][2] += a*b2; acc[j][3] += a*b3;
            }
        }
        #pragma unroll
        for (int j = 0; j < 4; j++) {
            int n = n0 + ng*4 + j;
            if (n >= N) continue;
            float f  = INV_S96 * sAt[ng*4+j];
            float al = sAl[ng*4+j];
            #pragma unroll
            for (int m = 0; m < 4; m++) {
                int o = cg*4 + m;
                float val = g_scs[n*OS + o] + al * (acc[j][m] * f);
                if (LAST) out[n*160 + o] = val;
                else      g_s1[n*96 + o] = val;
            }
        }
    }

    // vector: per plane i, (64 x 96) @ (96 x 32)  — plane-major Mv gather
    for (int i = 0; i < 3; i++) {
        __syncthreads();
        for (int idx = t; idx < 64*96; idx += 256) {
            int ln = idx / 96, u = idx - ln*96;
            int n = n0 + ln;
            sMv[ln*97 + u] = (n < N) ? g_Mv[n*288 + i*96 + u] * sIv[ln] : 0.f;
        }
        __syncthreads();
        int cg = t & 15, ng = t >> 4;
        float acc[4][2];
        #pragma unroll
        for (int j = 0; j < 4; j++) { acc[j][0]=0; acc[j][1]=0; }
        #pragma unroll 8
        for (int k = 0; k < 96; k++) {
            float b0 = sWv[k*32 + cg*2 + 0];
            float b1 = sWv[k*32 + cg*2 + 1];
            #pragma unroll
            for (int j = 0; j < 4; j++) {
                float a = sMv[(ng*4+j)*97 + k];
                acc[j][0] += a*b0; acc[j][1] += a*b1;
            }
        }
        #pragma unroll
        for (int j = 0; j < 4; j++) {
            int n = n0 + ng*4 + j;
            if (n >= N) continue;
            float f  = INV_S96 * sAt[ng*4+j];
            float al = sAl[ng*4+j];
            #pragma unroll
            for (int m = 0; m < 2; m++) {
                int kk = cg*2 + m;
                float val = g_scv[n*96 + kk*3 + i] + al * (acc[j][m] * f);
                if (LAST) out[n*160 + 64 + kk*3 + i] = val;
                else      g_v1[n*96 + kk*3 + i] = val;
            }
        }
    }
}

// ---------------- launch ----------------
static constexpr int NP_SMEM(int OS) { return (64*65 + 3*64*33 + 64*(64+OS) + 32*64 + 64) * 4; }
static constexpr int NF_SMEM(int OS) { return (64*97*2 + 96*OS + 96*32 + 96 + 64*3) * 4; }
static constexpr int EDGE_SMEM = (640 + 640 + 4096 + 64*192) * 4;

extern "C" void kernel_launch(void* const* d_in, const int* in_sizes, int n_in,
                              void* d_out, int out_size)
{
    const float* node_s = (const float*)d_in[0];
    const float* node_v = (const float*)d_in[1];
    const float* attr   = (const float*)d_in[2];
    const int*   src    = (const int*)d_in[3];
    const int*   dst    = (const int*)d_in[4];
    const float* sh     = (const float*)d_in[5];
    const float* esc    = (const float*)d_in[6];
    const float* p[18];
    for (int i = 0; i < 18; i++) p[i] = (const float*)d_in[7 + i];
    int N = in_sizes[0] / 64;
    int E = in_sizes[3];
    float* out = (float*)d_out;

    cudaFuncSetAttribute(k_nodeprep<96,false>, cudaFuncAttributeMaxDynamicSharedMemorySize, NP_SMEM(96));
    cudaFuncSetAttribute(k_nodeprep<64,true>,  cudaFuncAttributeMaxDynamicSharedMemorySize, NP_SMEM(64));
    cudaFuncSetAttribute(k_w,                  cudaFuncAttributeMaxDynamicSharedMemorySize, EDGE_SMEM);
    cudaFuncSetAttribute(k_nodefinal<96,false>,cudaFuncAttributeMaxDynamicSharedMemorySize, NF_SMEM(96));
    cudaFuncSetAttribute(k_nodefinal<64,true>, cudaFuncAttributeMaxDynamicSharedMemorySize, NF_SMEM(64));

    int nb_nodes = (N + 63) / 64;
    int nb_edges = (E + 63) / 64;
    int nb_agg   = (N + 7) / 8;        // 8 warps per 256-thread block

    // ---- CSR build (once; shared by both layers) ----
    k_cnt_zero<<<128, 256>>>(N);
    k_count<<<(E + 255) / 256, 256>>>(dst, E);
    k_scan<<<1, 1024>>>(N);
    k_fill<<<(E + 255) / 256, 256>>>(dst, E);

    // ---- layer 1 ----
    k_nodeprep<96,false><<<nb_nodes, 256, NP_SMEM(96)>>>(node_s, node_v, attr,
                                                         p[2], p[3], p[0], p[1], N);
    k_w<<<nb_edges, 384, EDGE_SMEM>>>(esc, p[4], p[5], E);
    k_agg<<<nb_agg, 256>>>(sh, src, N);
    k_nodefinal<96,false><<<nb_nodes, 256, NF_SMEM(96)>>>(attr, p[6], p[7], p[8], nullptr, N);

    // ---- layer 2 ----
    k_nodeprep<64,true><<<nb_nodes, 256, NP_SMEM(64)>>>(nullptr, nullptr, attr,
                                                        p[11], p[12], p[9], p[10], N);
    k_w<<<nb_edges, 384, EDGE_SMEM>>>(esc, p[13], p[14], E);
    k_agg<<<nb_agg, 256>>>(sh, src, N);
    k_nodefinal<64,true><<<nb_nodes, 256, NF_SMEM(64)>>>(attr, p[15], p[16], p[17], out, N);
}

// round 8
// speedup vs baseline: 1.1193x; 1.1193x over previous
#include <cuda_runtime.h>
#include <math.h>

#define NMAX 50000
#define EMAX 400000

// ---------------- scratch (device globals; no allocs allowed) ----------------
__device__ float g_hs [NMAX*64];   // lin1 scalar features (gather source)
__device__ float g_hv [NMAX*96];   // lin1 vector features [n][u*3+i], u<32
__device__ float g_scs[NMAX*96];   // skip scalar (stride OS per layer)
__device__ float g_scv[NMAX*96];   // skip vector [n][k*3+i]
__device__ float g_Ms [NMAX*96];   // scalar message accum
__device__ float g_Mv [NMAX*288];  // vector message accum, PLANE-MAJOR [n][i*96+u]
__device__ float g_s1 [NMAX*96];   // layer1 scalar output
__device__ float g_v1 [NMAX*96];   // layer1 vector output
__device__ float g_deg[NMAX];

// CSR (built once, shared by both layers)
__device__ int g_cnt   [NMAX];
__device__ int g_cur   [NMAX];
__device__ int g_rowptr[NMAX+1];
__device__ int g_eid   [EMAX];

__device__ __forceinline__ float siluf(float x)   { return x / (1.f + __expf(-x)); }
__device__ __forceinline__ float sigmf(float x)   { return 1.f / (1.f + __expf(-x)); }

#define INV_S10 0.31622776601683794f
#define INV_S32 0.17677669529663687f
#define INV_S96 0.10206207261596575f
#define INV_S3  0.57735026918962576f

// ---- packed f32x2 helpers ----
__device__ __forceinline__ unsigned long long pack2(float lo, float hi) {
    unsigned long long r;
    asm("mov.b64 %0, {%1, %2};" : "=l"(r) : "f"(lo), "f"(hi));
    return r;
}
__device__ __forceinline__ void fma2(unsigned long long &d,
                                     unsigned long long a, unsigned long long b) {
    asm("fma.rn.f32x2 %0, %1, %2, %0;" : "+l"(d) : "l"(a), "l"(b));
}
__device__ __forceinline__ float2 unpack2(unsigned long long v) {
    float2 r;
    asm("mov.b64 {%0, %1}, %2;" : "=f"(r.x), "=f"(r.y) : "l"(v));
    return r;
}

// ---------------- CSR build ----------------
__global__ void k_cnt_zero(int N)
{
    int i = blockIdx.x * blockDim.x + threadIdx.x;
    int stride = gridDim.x * blockDim.x;
    for (int j = i; j < N; j += stride) g_cnt[j] = 0;
}

__global__ void k_count(const int* __restrict__ dst, int E)
{
    int i = blockIdx.x * blockDim.x + threadIdx.x;
    if (i < E) atomicAdd(&g_cnt[dst[i]], 1);
}

__global__ void k_scan(int N)   // single block, 1024 threads
{
    __shared__ int part[1024];
    int t = threadIdx.x;
    int chunk = (N + 1023) >> 10;
    int b = t * chunk, e2 = min(b + chunk, N);
    int s = 0;
    for (int i = b; i < e2; i++) s += g_cnt[i];
    part[t] = s;
    __syncthreads();
    for (int off = 1; off < 1024; off <<= 1) {
        int v = (t >= off) ? part[t - off] : 0;
        __syncthreads();
        part[t] += v;
        __syncthreads();
    }
    int base = (t == 0) ? 0 : part[t - 1];
    for (int i = b; i < e2; i++) {
        int c = g_cnt[i];
        g_rowptr[i] = base;
        g_cur[i]    = base;
        g_deg[i]    = (float)max(c, 1);
        base += c;
    }
    if (t == 0) g_rowptr[N] = part[1023];
}

__global__ void k_fill(const int* __restrict__ dst, int E)
{
    int i = blockIdx.x * blockDim.x + threadIdx.x;
    if (i < E) {
        int p = atomicAdd(&g_cur[dst[i]], 1);
        g_eid[p] = i;
    }
}

// ---------------- zero Ms/Mv ----------------
__global__ void k_zero(int n)
{
    int stride = gridDim.x * blockDim.x;
    int i = blockIdx.x * blockDim.x + threadIdx.x;
    float4 z = make_float4(0.f, 0.f, 0.f, 0.f);
    int m1 = n * 24;
    for (int j = i; j < m1; j += stride) ((float4*)g_Ms)[j] = z;
    int m2 = n * 72;
    for (int j = i; j < m2; j += stride) ((float4*)g_Mv)[j] = z;
}

// ---------------- node prep: hs/hv + skip connections ----------------
template<int OS, bool L2IN>
__global__ __launch_bounds__(256) void k_nodeprep(
    const float* __restrict__ ns_in, const float* __restrict__ nv_in,
    const float* __restrict__ attr,
    const float* __restrict__ Wl1s, const float* __restrict__ Wl1v,
    const float* __restrict__ Wscs, const float* __restrict__ Wscv, int N)
{
    constexpr int WT = 64 + OS;
    extern __shared__ float sm[];
    float* sA  = sm;                 // [64][65]
    float* sV  = sA + 64*65;         // [3][64][33]
    float* sWs = sV + 3*64*33;       // [64][WT]
    float* sWv = sWs + 64*WT;        // [32][64]
    float* sAt = sWv + 32*64;        // [64]
    int t  = threadIdx.x;
    int n0 = blockIdx.x * 64;

    for (int idx = t; idx < 64*WT; idx += 256) {
        int u = idx / WT, o = idx - u*WT;
        sWs[idx] = (o < 64) ? Wl1s[u*64 + o] : Wscs[u*OS + (o-64)];
    }
    for (int idx = t; idx < 2048; idx += 256) {
        int u = idx >> 6, o = idx & 63;
        sWv[idx] = (o < 32) ? Wl1v[u*32 + o] : Wscv[u*32 + (o-32)];
    }
    for (int idx = t; idx < 4096; idx += 256) {
        int ln = idx >> 6, u = idx & 63;
        int n = n0 + ln; float v = 0.f;
        if (n < N) v = L2IN ? siluf(g_s1[n*96 + u]) : ns_in[n*64 + u];
        sA[ln*65 + u] = v;
    }
    for (int idx = t; idx < 2048; idx += 256) {
        int ln = idx >> 5, u = idx & 31;
        int n = n0 + ln;
        float a0 = 0.f, a1 = 0.f, a2 = 0.f;
        if (n < N) {
            if (L2IN) {
                float g = sigmf(g_s1[n*96 + 64 + u]);
                a0 = g_v1[n*96 + u*3+0] * g;
                a1 = g_v1[n*96 + u*3+1] * g;
                a2 = g_v1[n*96 + u*3+2] * g;
            } else {
                a0 = nv_in[(n*32+u)*3+0];
                a1 = nv_in[(n*32+u)*3+1];
                a2 = nv_in[(n*32+u)*3+2];
            }
        }
        sV[(0*64+ln)*33 + u] = a0;
        sV[(1*64+ln)*33 + u] = a1;
        sV[(2*64+ln)*33 + u] = a2;
    }
    if (t < 64) { int n = n0 + t; sAt[t] = (n < N) ? attr[n] : 0.f; }
    __syncthreads();

    constexpr int CG = WT / 4;
    for (int tid = t; tid < 16*CG; tid += 256) {
        int cg = tid % CG, ng = tid / CG;
        float acc[4][4];
        #pragma unroll
        for (int j = 0; j < 4; j++) { acc[j][0]=0;acc[j][1]=0;acc[j][2]=0;acc[j][3]=0; }
        #pragma unroll 8
        for (int k = 0; k < 64; k++) {
            float b0 = sWs[k*WT + cg*4 + 0];
            float b1 = sWs[k*WT + cg*4 + 1];
            float b2 = sWs[k*WT + cg*4 + 2];
            float b3 = sWs[k*WT + cg*4 + 3];
            #pragma unroll
            for (int j = 0; j < 4; j++) {
                float a = sA[(ng*4+j)*65 + k];
                acc[j][0] += a*b0; acc[j][1] += a*b1; acc[j][2] += a*b2; acc[j][3] += a*b3;
            }
        }
        #pragma unroll
        for (int j = 0; j < 4; j++) {
            int n = n0 + ng*4 + j;
            if (n >= N) continue;
            float f = sAt[ng*4+j] * 0.125f;
            #pragma unroll
            for (int m = 0; m < 4; m++) {
                int o = cg*4 + m;
                float v = acc[j][m] * f;
                if (o < 64) g_hs[n*64 + o] = v;
                else        g_scs[n*OS + (o-64)] = v;
            }
        }
    }

    {
        int cg = t & 15, ng = t >> 4;
        #pragma unroll
        for (int i = 0; i < 3; i++) {
            float acc[4][4];
            #pragma unroll
            for (int j = 0; j < 4; j++) { acc[j][0]=0;acc[j][1]=0;acc[j][2]=0;acc[j][3]=0; }
            #pragma unroll 8
            for (int k = 0; k < 32; k++) {
                float b0 = sWv[k*64 + cg*4 + 0];
                float b1 = sWv[k*64 + cg*4 + 1];
                float b2 = sWv[k*64 + cg*4 + 2];
                float b3 = sWv[k*64 + cg*4 + 3];
                #pragma unroll
                for (int j = 0; j < 4; j++) {
                    float a = sV[(i*64 + ng*4+j)*33 + k];
                    acc[j][0] += a*b0; acc[j][1] += a*b1; acc[j][2] += a*b2; acc[j][3] += a*b3;
                }
            }
            #pragma unroll
            for (int j = 0; j < 4; j++) {
                int n = n0 + ng*4 + j;
                if (n >= N) continue;
                float f = sAt[ng*4+j] * INV_S32;
                #pragma unroll
                for (int m = 0; m < 4; m++) {
                    int o = cg*4 + m;
                    float v = acc[j][m] * f;
                    if (o < 32) g_hv [n*96 + o*3 + i]      = v;
                    else        g_scv[n*96 + (o-32)*3 + i] = v;
                }
            }
        }
    }
}

// ---------------- fused edge kernel, CSR order: MLP + message + run-aggregated RED ----------------
__global__ __launch_bounds__(384, 2) void k_edge(
    const float* __restrict__ esc, const float* __restrict__ sh,
    const int* __restrict__ src, const int* __restrict__ dst,
    const float* __restrict__ Wfc1, const float* __restrict__ Wfc2, int E)
{
    extern __shared__ float sm[];
    float* s_W1  = sm;               // [10][64]
    float* s_esc = s_W1 + 640;       // [64][10]
    float* s_h   = s_esc + 640;      // [64 k][64 e]  (transposed)
    float* s_w   = s_h + 4096;       // [64 e][192]
    __shared__ int s_eid[64];
    __shared__ int s_src[64];
    __shared__ int s_dst[64];
    int t  = threadIdx.x;
    int e0 = blockIdx.x * 64;        // CSR slot base
    int nE = min(64, E - e0);

    // phase 0: gather edge ids / src / dst (CSR order)
    if (t < 64) {
        int p = e0 + t;
        int e = (t < nE) ? __ldg(&g_eid[p]) : -1;
        s_eid[t] = e;
        s_src[t] = (e >= 0) ? __ldg(&src[e]) : 0;
        s_dst[t] = (e >= 0) ? __ldg(&dst[e]) : -1;
    }
    for (int idx = t; idx < 640; idx += 384) s_W1[idx] = Wfc1[idx];
    __syncthreads();

    // esc gather (scattered rows, L2-resident)
    for (int idx = t; idx < 640; idx += 384) {
        int j = idx / 10, c = idx - j*10;
        int e = s_eid[j];
        s_esc[idx] = (e >= 0) ? __ldg(&esc[(size_t)e*10 + c]) : 0.f;
    }
    __syncthreads();

    // phase 1: h = silu(esc @ Wfc1 / sqrt(10))   store transposed s_h[o][e]
    for (int idx = t; idx < 4096; idx += 384) {
        int e = idx & 63, o = idx >> 6;
        float a = 0.f;
        #pragma unroll
        for (int j = 0; j < 10; j++) a += s_esc[e*10 + j] * s_W1[j*64 + o];
        s_h[o*64 + e] = siluf(a * INV_S10);
    }
    __syncthreads();

    // phase 2: w = h @ Wfc2 / 8   (64 edges x 192), pair-packed f32x2 FMA
    {
        int cg = t % 48;
        int eg = t / 48;   // 0..7
        unsigned long long acc[4][4];
        #pragma unroll
        for (int p = 0; p < 4; p++)
            #pragma unroll
            for (int c = 0; c < 4; c++) acc[p][c] = 0ull;
        const float4* W2 = reinterpret_cast<const float4*>(Wfc2) + cg;
        #pragma unroll 4
        for (int k = 0; k < 64; k++) {
            float4 b = __ldg(W2 + k*48);
            unsigned long long b2[4];
            b2[0] = pack2(b.x, b.x); b2[1] = pack2(b.y, b.y);
            b2[2] = pack2(b.z, b.z); b2[3] = pack2(b.w, b.w);
            const unsigned long long* hp =
                reinterpret_cast<const unsigned long long*>(s_h + k*64 + eg*8);
            ulonglong2 hA = *reinterpret_cast<const ulonglong2*>(hp);
            ulonglong2 hB = *reinterpret_cast<const ulonglong2*>(hp + 2);
            unsigned long long h2[4] = {hA.x, hA.y, hB.x, hB.y};
            #pragma unroll
            for (int p = 0; p < 4; p++) {
                fma2(acc[p][0], h2[p], b2[0]);
                fma2(acc[p][1], h2[p], b2[1]);
                fma2(acc[p][2], h2[p], b2[2]);
                fma2(acc[p][3], h2[p], b2[3]);
            }
        }
        #pragma unroll
        for (int p = 0; p < 4; p++) {
            float* w0 = s_w + (eg*8 + 2*p)     * 192 + cg*4;
            float* w1 = s_w + (eg*8 + 2*p + 1) * 192 + cg*4;
            #pragma unroll
            for (int c = 0; c < 4; c++) {
                float2 v = unpack2(acc[p][c]);
                w0[c] = v.x * 0.125f;
                w1[c] = v.y * 0.125f;
            }
        }
    }
    __syncthreads();

    // phase 3: 8 warps x 8 consecutive CSR edges; register-accumulate same-dst runs
    int warp = t >> 5, lane = t & 31;
    if (warp < 8) {
        float as0=0.f, as1=0.f, as2=0.f;
        float av00=0.f, av01=0.f, av02=0.f;
        float av10=0.f, av11=0.f, av12=0.f;
        float av20=0.f, av21=0.f, av22=0.f;
        int cur = -1;

        int jbeg = warp * 8;
        int jend = min(jbeg + 8, nE);
        for (int j = jbeg; j < jend; j++) {
            int d = s_dst[j];
            if (d != cur) {
                if (cur >= 0) {
                    float* Msd = g_Ms + (size_t)cur * 96;
                    atomicAdd(Msd + lane,      as0);
                    atomicAdd(Msd + 32 + lane, as1);
                    atomicAdd(Msd + 64 + lane, as2);
                    float* Mvd = g_Mv + (size_t)cur * 288;
                    atomicAdd(Mvd +        lane, av00);
                    atomicAdd(Mvd +  32 + lane, av01);
                    atomicAdd(Mvd +  64 + lane, av02);
                    atomicAdd(Mvd +  96 + lane, av10);
                    atomicAdd(Mvd + 128 + lane, av11);
                    atomicAdd(Mvd + 160 + lane, av12);
                    atomicAdd(Mvd + 192 + lane, av20);
                    atomicAdd(Mvd + 224 + lane, av21);
                    atomicAdd(Mvd + 256 + lane, av22);
                }
                as0=as1=as2=0.f;
                av00=av01=av02=av10=av11=av12=av20=av21=av22=0.f;
                cur = d;
            }
            int s = s_src[j];
            int e = s_eid[j];
            float4 sh4 = __ldg(reinterpret_cast<const float4*>(sh) + e);
            float sh0 = sh4.x, shx = sh4.y, shy = sh4.z, shz = sh4.w;

            const float* wr = s_w + j * 192;
            float w1a = wr[lane];
            float w1b = wr[32 + lane];
            float w2a = wr[64 + lane];
            float w2b = wr[96 + lane];
            float w3  = wr[128 + lane];
            float w4  = wr[160 + lane];

            const float* hsp = g_hs + (size_t)s * 64;
            float gs0 = __ldg(hsp + lane);
            float gs1 = __ldg(hsp + 32 + lane);
            const float* hvp = g_hv + (size_t)s * 96 + lane*3;
            float gv0 = __ldg(hvp + 0);
            float gv1 = __ldg(hvp + 1);
            float gv2 = __ldg(hvp + 2);

            as0 += gs0 * sh0 * w1a;
            as1 += gs1 * sh0 * w1b;
            as2 += (gv0*shx + gv1*shy + gv2*shz) * INV_S3 * w4;
            float p0 = gs0 * w2a, p1 = gs1 * w2b, g3 = sh0 * w3;
            av00 += p0 * shx;  av01 += p1 * shx;  av02 += gv0 * g3;
            av10 += p0 * shy;  av11 += p1 * shy;  av12 += gv1 * g3;
            av20 += p0 * shz;  av21 += p1 * shz;  av22 += gv2 * g3;
        }
        if (cur >= 0) {
            float* Msd = g_Ms + (size_t)cur * 96;
            atomicAdd(Msd + lane,      as0);
            atomicAdd(Msd + 32 + lane, as1);
            atomicAdd(Msd + 64 + lane, as2);
            float* Mvd = g_Mv + (size_t)cur * 288;
            atomicAdd(Mvd +        lane, av00);
            atomicAdd(Mvd +  32 + lane, av01);
            atomicAdd(Mvd +  64 + lane, av02);
            atomicAdd(Mvd +  96 + lane, av10);
            atomicAdd(Mvd + 128 + lane, av11);
            atomicAdd(Mvd + 160 + lane, av12);
            atomicAdd(Mvd + 192 + lane, av20);
            atomicAdd(Mvd + 224 + lane, av21);
            atomicAdd(Mvd + 256 + lane, av22);
        }
    }
}

// ---------------- node finalize: mean, alpha, lin2, skip add ----------------
template<int OS, bool LAST>
__global__ __launch_bounds__(256) void k_nodefinal(
    const float* __restrict__ attr,
    const float* __restrict__ Wl2s,   // [96][OS]
    const float* __restrict__ Wl2v,   // [96][32]
    const float* __restrict__ Wa,     // [96]
    float* __restrict__ out, int N)
{
    extern __shared__ float sm[];
    float* sMs = sm;                  // [64][97]
    float* sMv = sMs + 64*97;         // [64][97]
    float* sWs = sMv + 64*97;         // [96][OS]
    float* sWv = sWs + 96*OS;         // [96][32]
    float* sWa = sWv + 96*32;         // [96]
    float* sAl = sWa + 96;            // [64]
    float* sIv = sAl + 64;            // [64]
    float* sAt = sIv + 64;            // [64]
    int t  = threadIdx.x;
    int n0 = blockIdx.x * 64;

    for (int idx = t; idx < 96*OS; idx += 256) sWs[idx] = Wl2s[idx];
    for (int idx = t; idx < 96*32; idx += 256) sWv[idx] = Wl2v[idx];
    if (t < 96) sWa[t] = Wa[t];
    if (t < 64) {
        int n = n0 + t;
        sIv[t] = (n < N) ? 1.f / fmaxf(g_deg[n], 1.f) : 0.f;
        sAt[t] = (n < N) ? attr[n] : 0.f;
    }
    __syncthreads();
    for (int idx = t; idx < 64*96; idx += 256) {
        int ln = idx / 96, j = idx - ln*96;
        int n = n0 + ln;
        sMs[ln*97 + j] = (n < N) ? g_Ms[n*96 + j] * sIv[ln] : 0.f;
    }
    __syncthreads();
    if (t < 64) {
        float a = 0.f;
        #pragma unroll 8
        for (int j = 0; j < 96; j++) a += sMs[t*97 + j] * sWa[j];
        sAl[t] = a * INV_S96 * sAt[t];
    }
    __syncthreads();

    constexpr int CG = OS / 4;
    for (int tid = t; tid < 16*CG; tid += 256) {
        int cg = tid % CG, ng = tid / CG;
        float acc[4][4];
        #pragma unroll
        for (int j = 0; j < 4; j++) { acc[j][0]=0;acc[j][1]=0;acc[j][2]=0;acc[j][3]=0; }
        #pragma unroll 8
        for (int k = 0; k < 96; k++) {
            float b0 = sWs[k*OS + cg*4 + 0];
            float b1 = sWs[k*OS + cg*4 + 1];
            float b2 = sWs[k*OS + cg*4 + 2];
            float b3 = sWs[k*OS + cg*4 + 3];
            #pragma unroll
            for (int j = 0; j < 4; j++) {
                float a = sMs[(ng*4+j)*97 + k];
                acc[j][0] += a*b0; acc[j][1] += a*b1; acc[j][2] += a*b2; acc[j][3] += a*b3;
            }
        }
        #pragma unroll
        for (int j = 0; j < 4; j++) {
            int n = n0 + ng*4 + j;
            if (n >= N) continue;
            float f  = INV_S96 * sAt[ng*4+j];
            float al = sAl[ng*4+j];
            #pragma unroll
            for (int m = 0; m < 4; m++) {
                int o = cg*4 + m;
                float val = g_scs[n*OS + o] + al * (acc[j][m] * f);
                if (LAST) out[n*160 + o] = val;
                else      g_s1[n*96 + o] = val;
            }
        }
    }

    // vector: per plane i, (64 x 96) @ (96 x 32)  — plane-major Mv gather
    for (int i = 0; i < 3; i++) {
        __syncthreads();
        for (int idx = t; idx < 64*96; idx += 256) {
            int ln = idx / 96, u = idx - ln*96;
            int n = n0 + ln;
            sMv[ln*97 + u] = (n < N) ? g_Mv[n*288 + i*96 + u] * sIv[ln] : 0.f;
        }
        __syncthreads();
        int cg = t & 15, ng = t >> 4;
        float acc[4][2];
        #pragma unroll
        for (int j = 0; j < 4; j++) { acc[j][0]=0; acc[j][1]=0; }
        #pragma unroll 8
        for (int k = 0; k < 96; k++) {
            float b0 = sWv[k*32 + cg*2 + 0];
            float b1 = sWv[k*32 + cg*2 + 1];
            #pragma unroll
            for (int j = 0; j < 4; j++) {
                float a = sMv[(ng*4+j)*97 + k];
                acc[j][0] += a*b0; acc[j][1] += a*b1;
            }
        }
        #pragma unroll
        for (int j = 0; j < 4; j++) {
            int n = n0 + ng*4 + j;
            if (n >= N) continue;
            float f  = INV_S96 * sAt[ng*4+j];
            float al = sAl[ng*4+j];
            #pragma unroll
            for (int m = 0; m < 2; m++) {
                int kk = cg*2 + m;
                float val = g_scv[n*96 + kk*3 + i] + al * (acc[j][m] * f);
                if (LAST) out[n*160 + 64 + kk*3 + i] = val;
                else      g_v1[n*96 + kk*3 + i] = val;
            }
        }
    }
}

// ---------------- launch ----------------
static constexpr int NP_SMEM(int OS) { return (64*65 + 3*64*33 + 64*(64+OS) + 32*64 + 64) * 4; }
static constexpr int NF_SMEM(int OS) { return (64*97*2 + 96*OS + 96*32 + 96 + 64*3) * 4; }
static constexpr int EDGE_SMEM = (640 + 640 + 4096 + 64*192) * 4;

extern "C" void kernel_launch(void* const* d_in, const int* in_sizes, int n_in,
                              void* d_out, int out_size)
{
    const float* node_s = (const float*)d_in[0];
    const float* node_v = (const float*)d_in[1];
    const float* attr   = (const float*)d_in[2];
    const int*   src    = (const int*)d_in[3];
    const int*   dst    = (const int*)d_in[4];
    const float* sh     = (const float*)d_in[5];
    const float* esc    = (const float*)d_in[6];
    const float* p[18];
    for (int i = 0; i < 18; i++) p[i] = (const float*)d_in[7 + i];
    int N = in_sizes[0] / 64;
    int E = in_sizes[3];
    float* out = (float*)d_out;

    cudaFuncSetAttribute(k_nodeprep<96,false>, cudaFuncAttributeMaxDynamicSharedMemorySize, NP_SMEM(96));
    cudaFuncSetAttribute(k_nodeprep<64,true>,  cudaFuncAttributeMaxDynamicSharedMemorySize, NP_SMEM(64));
    cudaFuncSetAttribute(k_edge,               cudaFuncAttributeMaxDynamicSharedMemorySize, EDGE_SMEM);
    cudaFuncSetAttribute(k_nodefinal<96,false>,cudaFuncAttributeMaxDynamicSharedMemorySize, NF_SMEM(96));
    cudaFuncSetAttribute(k_nodefinal<64,true>, cudaFuncAttributeMaxDynamicSharedMemorySize, NF_SMEM(64));

    int nb_nodes = (N + 63) / 64;
    int nb_edges = (E + 63) / 64;

    // ---- CSR build (once; shared by both layers; also produces g_deg) ----
    k_cnt_zero<<<128, 256>>>(N);
    k_count<<<(E + 255) / 256, 256>>>(dst, E);
    k_scan<<<1, 1024>>>(N);
    k_fill<<<(E + 255) / 256, 256>>>(dst, E);

    // ---- layer 1 ----
    k_zero<<<512, 256>>>(N);
    k_nodeprep<96,false><<<nb_nodes, 256, NP_SMEM(96)>>>(node_s, node_v, attr,
                                                         p[2], p[3], p[0], p[1], N);
    k_edge<<<nb_edges, 384, EDGE_SMEM>>>(esc, sh, src, dst, p[4], p[5], E);
    k_nodefinal<96,false><<<nb_nodes, 256, NF_SMEM(96)>>>(attr, p[6], p[7], p[8], nullptr, N);

    // ---- layer 2 ----
    k_zero<<<512, 256>>>(N);
    k_nodeprep<64,true><<<nb_nodes, 256, NP_SMEM(64)>>>(nullptr, nullptr, attr,
                                                        p[11], p[12], p[9], p[10], N);
    k_edge<<<nb_edges, 384, EDGE_SMEM>>>(esc, sh, src, dst, p[13], p[14], E);
    k_nodefinal<64,true><<<nb_nodes, 256, NF_SMEM(64)>>>(attr, p[15], p[16], p[17], out, N);
}

// round 15
// speedup vs baseline: 1.1876x; 1.0610x over previous
#include <cuda_runtime.h>
#include <math.h>

#define NMAX 50000
#define EMAX 400000

// ---------------- scratch (device globals; no allocs allowed) ----------------
__device__ float g_hs [NMAX*64];   // lin1 scalar features (gather source)
__device__ float g_hv [NMAX*96];   // lin1 vector features [n][u*3+i], u<32
__device__ float g_scs[NMAX*96];   // skip scalar (stride OS per layer)
__device__ float g_scv[NMAX*96];   // skip vector [n][k*3+i]
__device__ float g_Ms [NMAX*96];   // scalar message accum
__device__ float g_Mv [NMAX*288];  // vector message accum, PLANE-MAJOR [n][i*96+u]
__device__ float g_s1 [NMAX*96];   // layer1 scalar output
__device__ float g_v1 [NMAX*96];   // layer1 vector output
__device__ float g_deg[NMAX];

__device__ __forceinline__ float siluf(float x)   { return x / (1.f + __expf(-x)); }
__device__ __forceinline__ float sigmf(float x)   { return 1.f / (1.f + __expf(-x)); }

#define INV_S10 0.31622776601683794f
#define INV_S32 0.17677669529663687f
#define INV_S96 0.10206207261596575f
#define INV_S3  0.57735026918962576f

// ---- packed f32x2 helpers ----
__device__ __forceinline__ unsigned long long pack2(float lo, float hi) {
    unsigned long long r;
    asm("mov.b64 %0, {%1, %2};" : "=l"(r) : "f"(lo), "f"(hi));
    return r;
}
__device__ __forceinline__ void fma2(unsigned long long &d,
                                     unsigned long long a, unsigned long long b) {
    asm("fma.rn.f32x2 %0, %1, %2, %0;" : "+l"(d) : "l"(a), "l"(b));
}
__device__ __forceinline__ float2 unpack2(unsigned long long v) {
    float2 r;
    asm("mov.b64 {%0, %1}, %2;" : "=f"(r.x), "=f"(r.y) : "l"(v));
    return r;
}

// ---------------- zero Ms/Mv (+deg) ----------------
__global__ void k_zero(int n, int zdeg)
{
    int stride = gridDim.x * blockDim.x;
    int i = blockIdx.x * blockDim.x + threadIdx.x;
    float4 z = make_float4(0.f, 0.f, 0.f, 0.f);
    int m1 = n * 24;
    for (int j = i; j < m1; j += stride) ((float4*)g_Ms)[j] = z;
    int m2 = n * 72;
    for (int j = i; j < m2; j += stride) ((float4*)g_Mv)[j] = z;
    if (zdeg) for (int j = i; j < n; j += stride) g_deg[j] = 0.f;
}

__global__ void k_deg(const int* __restrict__ dst, int E)
{
    int i = blockIdx.x * blockDim.x + threadIdx.x;
    if (i < E) atomicAdd(&g_deg[dst[i]], 1.f);
}

// ---------------- node prep: hs/hv + skip connections (f32x2 GEMMs) ----------------
template<int OS, bool L2IN>
__global__ __launch_bounds__(256) void k_nodeprep(
    const float* __restrict__ ns_in, const float* __restrict__ nv_in,
    const float* __restrict__ attr,
    const float* __restrict__ Wl1s, const float* __restrict__ Wl1v,
    const float* __restrict__ Wscs, const float* __restrict__ Wscv, int N)
{
    constexpr int WT = 64 + OS;
    extern __shared__ float sm[];
    float* sA  = sm;                 // [64][65]
    float* sV  = sA + 64*65;         // [3][64][33]
    float* sWs = sV + 3*64*33;       // [64][WT]
    float* sWv = sWs + 64*WT;        // [32][64]
    float* sAt = sWv + 32*64;        // [64]
    int t  = threadIdx.x;
    int n0 = blockIdx.x * 64;

    for (int idx = t; idx < 64*WT; idx += 256) {
        int u = idx / WT, o = idx - u*WT;
        sWs[idx] = (o < 64) ? Wl1s[u*64 + o] : Wscs[u*OS + (o-64)];
    }
    for (int idx = t; idx < 2048; idx += 256) {
        int u = idx >> 6, o = idx & 63;
        sWv[idx] = (o < 32) ? Wl1v[u*32 + o] : Wscv[u*32 + (o-32)];
    }
    for (int idx = t; idx < 4096; idx += 256) {
        int ln = idx >> 6, u = idx & 63;
        int n = n0 + ln; float v = 0.f;
        if (n < N) v = L2IN ? siluf(g_s1[n*96 + u]) : ns_in[n*64 + u];
        sA[ln*65 + u] = v;
    }
    for (int idx = t; idx < 2048; idx += 256) {
        int ln = idx >> 5, u = idx & 31;
        int n = n0 + ln;
        float a0 = 0.f, a1 = 0.f, a2 = 0.f;
        if (n < N) {
            if (L2IN) {
                float g = sigmf(g_s1[n*96 + 64 + u]);
                a0 = g_v1[n*96 + u*3+0] * g;
                a1 = g_v1[n*96 + u*3+1] * g;
                a2 = g_v1[n*96 + u*3+2] * g;
            } else {
                a0 = nv_in[(n*32+u)*3+0];
                a1 = nv_in[(n*32+u)*3+1];
                a2 = nv_in[(n*32+u)*3+2];
            }
        }
        sV[(0*64+ln)*33 + u] = a0;
        sV[(1*64+ln)*33 + u] = a1;
        sV[(2*64+ln)*33 + u] = a2;
    }
    if (t < 64) { int n = n0 + t; sAt[t] = (n < N) ? attr[n] : 0.f; }
    __syncthreads();

    // scalar: (64 x 64) @ (64 x WT), pair-packed f32x2
    constexpr int CG = WT / 4;
    for (int tid = t; tid < 16*CG; tid += 256) {
        int cg = tid % CG, ng = tid / CG;
        unsigned long long acc01[4], acc23[4];
        #pragma unroll
        for (int j = 0; j < 4; j++) { acc01[j] = 0ull; acc23[j] = 0ull; }
        #pragma unroll 8
        for (int k = 0; k < 64; k++) {
            const float* bp = sWs + k*WT + cg*4;
            unsigned long long b01 = pack2(bp[0], bp[1]);
            unsigned long long b23 = pack2(bp[2], bp[3]);
            #pragma unroll
            for (int j = 0; j < 4; j++) {
                float a = sA[(ng*4+j)*65 + k];
                unsigned long long a2 = pack2(a, a);
                fma2(acc01[j], a2, b01);
                fma2(acc23[j], a2, b23);
            }
        }
        #pragma unroll
        for (int j = 0; j < 4; j++) {
            int n = n0 + ng*4 + j;
            if (n >= N) continue;
            float f = sAt[ng*4+j] * 0.125f;
            float2 v01 = unpack2(acc01[j]);
            float2 v23 = unpack2(acc23[j]);
            float vv[4] = {v01.x, v01.y, v23.x, v23.y};
            #pragma unroll
            for (int m = 0; m < 4; m++) {
                int o = cg*4 + m;
                float v = vv[m] * f;
                if (o < 64) g_hs[n*64 + o] = v;
                else        g_scs[n*OS + (o-64)] = v;
            }
        }
    }

    // vector: per plane i, (64 x 32) @ (32 x 64), pair-packed f32x2
    {
        int cg = t & 15, ng = t >> 4;
        #pragma unroll
        for (int i = 0; i < 3; i++) {
            unsigned long long acc01[4], acc23[4];
            #pragma unroll
            for (int j = 0; j < 4; j++) { acc01[j] = 0ull; acc23[j] = 0ull; }
            #pragma unroll 8
            for (int k = 0; k < 32; k++) {
                const float* bp = sWv + k*64 + cg*4;
                unsigned long long b01 = pack2(bp[0], bp[1]);
                unsigned long long b23 = pack2(bp[2], bp[3]);
                #pragma unroll
                for (int j = 0; j < 4; j++) {
                    float a = sV[(i*64 + ng*4+j)*33 + k];
                    unsigned long long a2 = pack2(a, a);
                    fma2(acc01[j], a2, b01);
                    fma2(acc23[j], a2, b23);
                }
            }
            #pragma unroll
            for (int j = 0; j < 4; j++) {
                int n = n0 + ng*4 + j;
                if (n >= N) continue;
                float f = sAt[ng*4+j] * INV_S32;
                float2 v01 = unpack2(acc01[j]);
                float2 v23 = unpack2(acc23[j]);
                float vv[4] = {v01.x, v01.y, v23.x, v23.y};
                #pragma unroll
                for (int m = 0; m < 4; m++) {
                    int o = cg*4 + m;
                    float v = vv[m] * f;
                    if (o < 32) g_hv [n*96 + o*3 + i]      = v;
                    else        g_scv[n*96 + (o-32)*3 + i] = v;
                }
            }
        }
    }
}

// ---------------- edge kernel (round-4 verbatim) ----------------
__global__ __launch_bounds__(384, 2) void k_edge(
    const float* __restrict__ esc, const float* __restrict__ sh,
    const int* __restrict__ src, const int* __restrict__ dst,
    const float* __restrict__ Wfc1, const float* __restrict__ Wfc2, int E)
{
    extern __shared__ float sm[];
    float* s_W1  = sm;               // [10][64]
    float* s_esc = s_W1 + 640;       // [64][10]
    float* s_h   = s_esc + 640;      // [64 k][64 e]  (transposed)
    float* s_w   = s_h + 4096;       // [64 e][192]
    int t  = threadIdx.x;
    int e0 = blockIdx.x * 64;
    int nE = min(64, E - e0);

    for (int idx = t; idx < 640; idx += 384) s_W1[idx] = Wfc1[idx];
    for (int idx = t; idx < 640; idx += 384)
        s_esc[idx] = (idx < nE*10) ? esc[(long)e0*10 + idx] : 0.f;
    __syncthreads();

    // phase 1: h = silu(esc @ Wfc1 / sqrt(10))   store transposed s_h[o][e]
    for (int idx = t; idx < 4096; idx += 384) {
        int e = idx & 63, o = idx >> 6;
        float a = 0.f;
        #pragma unroll
        for (int j = 0; j < 10; j++) a += s_esc[e*10 + j] * s_W1[j*64 + o];
        s_h[o*64 + e] = siluf(a * INV_S10);
    }
    __syncthreads();

    // phase 2: w = h @ Wfc2 / 8   (64 edges x 192), pair-packed f32x2 FMA
    {
        int cg = t % 48;
        int eg = t / 48;   // 0..7
        unsigned long long acc[4][4];
        #pragma unroll
        for (int p = 0; p < 4; p++)
            #pragma unroll
            for (int c = 0; c < 4; c++) acc[p][c] = 0ull;
        const float4* W2 = reinterpret_cast<const float4*>(Wfc2) + cg;
        #pragma unroll 4
        for (int k = 0; k < 64; k++) {
            float4 b = __ldg(W2 + k*48);
            unsigned long long b2[4];
            b2[0] = pack2(b.x, b.x); b2[1] = pack2(b.y, b.y);
            b2[2] = pack2(b.z, b.z); b2[3] = pack2(b.w, b.w);
            const unsigned long long* hp =
                reinterpret_cast<const unsigned long long*>(s_h + k*64 + eg*8);
            ulonglong2 hA = *reinterpret_cast<const ulonglong2*>(hp);
            ulonglong2 hB = *reinterpret_cast<const ulonglong2*>(hp + 2);
            unsigned long long h2[4] = {hA.x, hA.y, hB.x, hB.y};
            #pragma unroll
            for (int p = 0; p < 4; p++) {
                fma2(acc[p][0], h2[p], b2[0]);
                fma2(acc[p][1], h2[p], b2[1]);
                fma2(acc[p][2], h2[p], b2[2]);
                fma2(acc[p][3], h2[p], b2[3]);
            }
        }
        #pragma unroll
        for (int p = 0; p < 4; p++) {
            float* w0 = s_w + (eg*8 + 2*p)     * 192 + cg*4;
            float* w1 = s_w + (eg*8 + 2*p + 1) * 192 + cg*4;
            #pragma unroll
            for (int c = 0; c < 4; c++) {
                float2 v = unpack2(acc[p][c]);
                w0[c] = v.x * 0.125f;
                w1[c] = v.y * 0.125f;
            }
        }
    }
    __syncthreads();

    // phase 3: warp per edge -> 96 float4 REDs (3 branch-uniform rounds)
    int warp = t >> 5, lane = t & 31;
    for (int e = warp; e < nE; e += 12) {
        int ee = e0 + e;
        int s = src[ee], d = dst[ee];
        float4 sh4 = __ldg(reinterpret_cast<const float4*>(sh) + ee);
        float sh0 = sh4.x, shx = sh4.y, shy = sh4.z, shz = sh4.w;
        const float* wr = s_w + e*192;
        const float4* hs4 = reinterpret_cast<const float4*>(g_hs + (size_t)s*64);
        float4* Msd = reinterpret_cast<float4*>(g_Ms + (size_t)d*96);
        float4* Mvd = reinterpret_cast<float4*>(g_Mv + (size_t)d*288);

        // ---- round 0: gs-Mv chunks, planes 0,1 ----
        {
            int i  = lane >> 4;          // 0 or 1
            int q  = lane & 15;          // u0 = 4q
            float shv_i = i ? shy : shx;
            float4 gs = __ldg(hs4 + q);
            float4 w2 = *reinterpret_cast<const float4*>(wr + 64 + 4*q);
            float4 v = make_float4(gs.x*w2.x*shv_i, gs.y*w2.y*shv_i,
                                   gs.z*w2.z*shv_i, gs.w*w2.w*shv_i);
            atomicAdd(Mvd + i*24 + q, v);
        }
        // ---- round 1: gs-Mv plane 2 (lanes 0-15) | gs-Ms (lanes 16-31) ----
        {
            int q = lane & 15;
            float4 gs = __ldg(hs4 + q);
            if (lane < 16) {
                float4 w2 = *reinterpret_cast<const float4*>(wr + 64 + 4*q);
                float4 v = make_float4(gs.x*w2.x*shz, gs.y*w2.y*shz,
                                       gs.z*w2.z*shz, gs.w*w2.w*shz);
                atomicAdd(Mvd + 48 + q, v);
            } else {
                float4 w1 = *reinterpret_cast<const float4*>(wr + 4*q);
                float4 v = make_float4(gs.x*w1.x*sh0, gs.y*w1.y*sh0,
                                       gs.z*w1.z*sh0, gs.w*w1.w*sh0);
                atomicAdd(Msd + q, v);
            }
        }
        // ---- round 2: dot-Ms (lanes 0-7) | gv-Mv (lanes 8-31) ----
        {
            int k0 = (lane < 8) ? (lane * 4) : (((lane - 8) & 7) * 4);
            const float4* gp = reinterpret_cast<const float4*>(
                g_hv + (size_t)s*96 + k0*3);
            float4 gA = __ldg(gp + 0);
            float4 gB = __ldg(gp + 1);
            float4 gC = __ldg(gp + 2);
            if (lane < 8) {
                float4 w4 = *reinterpret_cast<const float4*>(wr + 160 + k0);
                float d0 = gA.x*shx + gA.y*shy + gA.z*shz;
                float d1 = gA.w*shx + gB.x*shy + gB.y*shz;
                float d2 = gB.z*shx + gB.w*shy + gC.x*shz;
                float d3 = gC.y*shx + gC.z*shy + gC.w*shz;
                float4 v = make_float4(d0*INV_S3*w4.x, d1*INV_S3*w4.y,
                                       d2*INV_S3*w4.z, d3*INV_S3*w4.w);
                atomicAdd(Msd + 16 + (k0 >> 2), v);
            } else {
                int i = (lane - 8) >> 3;   // 0..2
                float g0 = (i==0) ? gA.x : ((i==1) ? gA.y : gA.z);
                float g1 = (i==0) ? gA.w : ((i==1) ? gB.x : gB.y);
                float g2 = (i==0) ? gB.z : ((i==1) ? gB.w : gC.x);
                float g3 = (i==0) ? gC.y : ((i==1) ? gC.z : gC.w);
                float4 w3 = *reinterpret_cast<const float4*>(wr + 128 + k0);
                float4 v = make_float4(g0*w3.x*sh0, g1*w3.y*sh0,
                                       g2*w3.z*sh0, g3*w3.w*sh0);
                atomicAdd(Mvd + i*24 + 16 + (k0 >> 2), v);
            }
        }
    }
}

// ---------------- node finalize: mean, alpha, lin2, skip add (f32x2 GEMMs) ----------------
template<int OS, bool LAST>
__global__ __launch_bounds__(256) void k_nodefinal(
    const float* __restrict__ attr,
    const float* __restrict__ Wl2s,   // [96][OS]
    const float* __restrict__ Wl2v,   // [96][32]
    const float* __restrict__ Wa,     // [96]
    float* __restrict__ out, int N)
{
    extern __shared__ float sm[];
    float* sMs = sm;                  // [64][97]
    float* sMv = sMs + 64*97;         // [64][97]
    float* sWs = sMv + 64*97;         // [96][OS]
    float* sWv = sWs + 96*OS;         // [96][32]
    float* sWa = sWv + 96*32;         // [96]
    float* sAl = sWa + 96;            // [64]
    float* sIv = sAl + 64;            // [64]
    float* sAt = sIv + 64;            // [64]
    int t  = threadIdx.x;
    int n0 = blockIdx.x * 64;

    for (int idx = t; idx < 96*OS; idx += 256) sWs[idx] = Wl2s[idx];
    for (int idx = t; idx < 96*32; idx += 256) sWv[idx] = Wl2v[idx];
    if (t < 96) sWa[t] = Wa[t];
    if (t < 64) {
        int n = n0 + t;
        sIv[t] = (n < N) ? 1.f / fmaxf(g_deg[n], 1.f) : 0.f;
        sAt[t] = (n < N) ? attr[n] : 0.f;
    }
    __syncthreads();
    for (int idx = t; idx < 64*96; idx += 256) {
        int ln = idx / 96, j = idx - ln*96;
        int n = n0 + ln;
        sMs[ln*97 + j] = (n < N) ? g_Ms[n*96 + j] * sIv[ln] : 0.f;
    }
    __syncthreads();
    if (t < 64) {
        float a = 0.f;
        #pragma unroll 8
        for (int j = 0; j < 96; j++) a += sMs[t*97 + j] * sWa[j];
        sAl[t] = a * INV_S96 * sAt[t];
    }
    __syncthreads();

    // scalar: (64 x 96) @ (96 x OS), pair-packed f32x2
    constexpr int CG = OS / 4;
    for (int tid = t; tid < 16*CG; tid += 256) {
        int cg = tid % CG, ng = tid / CG;
        unsigned long long acc01[4], acc23[4];
        #pragma unroll
        for (int j = 0; j < 4; j++) { acc01[j] = 0ull; acc23[j] = 0ull; }
        #pragma unroll 8
        for (int k = 0; k < 96; k++) {
            const float* bp = sWs + k*OS + cg*4;
            unsigned long long b01 = pack2(bp[0], bp[1]);
            unsigned long long b23 = pack2(bp[2], bp[3]);
            #pragma unroll
            for (int j = 0; j < 4; j++) {
                float a = sMs[(ng*4+j)*97 + k];
                unsigned long long a2 = pack2(a, a);
                fma2(acc01[j], a2, b01);
                fma2(acc23[j], a2, b23);
            }
        }
        #pragma unroll
        for (int j = 0; j < 4; j++) {
            int n = n0 + ng*4 + j;
            if (n >= N) continue;
            float f  = INV_S96 * sAt[ng*4+j];
            float al = sAl[ng*4+j];
            float2 v01 = unpack2(acc01[j]);
            float2 v23 = unpack2(acc23[j]);
            float vv[4] = {v01.x, v01.y, v23.x, v23.y};
            #pragma unroll
            for (int m = 0; m < 4; m++) {
                int o = cg*4 + m;
                float val = g_scs[n*OS + o] + al * (vv[m] * f);
                if (LAST) out[n*160 + o] = val;
                else      g_s1[n*96 + o] = val;
            }
        }
    }

    // vector: per plane i, (64 x 96) @ (96 x 32), pair-packed f32x2
    for (int i = 0; i < 3; i++) {
        __syncthreads();
        for (int idx = t; idx < 64*96; idx += 256) {
            int ln = idx / 96, u = idx - ln*96;
            int n = n0 + ln;
            sMv[ln*97 + u] = (n < N) ? g_Mv[n*288 + i*96 + u] * sIv[ln] : 0.f;
        }
        __syncthreads();
        int cg = t & 15, ng = t >> 4;
        unsigned long long acc[4];
        #pragma unroll
        for (int j = 0; j < 4; j++) acc[j] = 0ull;
        #pragma unroll 8
        for (int k = 0; k < 96; k++) {
            const float* bp = sWv + k*32 + cg*2;
            unsigned long long b01 = pack2(bp[0], bp[1]);
            #pragma unroll
            for (int j = 0; j < 4; j++) {
                float a = sMv[(ng*4+j)*97 + k];
                unsigned long long a2 = pack2(a, a);
                fma2(acc[j], a2, b01);
            }
        }
        #pragma unroll
        for (int j = 0; j < 4; j++) {
            int n = n0 + ng*4 + j;
            if (n >= N) continue;
            float f  = INV_S96 * sAt[ng*4+j];
            float al = sAl[ng*4+j];
            float2 v01 = unpack2(acc[j]);
            float vv[2] = {v01.x, v01.y};
            #pragma unroll
            for (int m = 0; m < 2; m++) {
                int kk = cg*2 + m;
                float val = g_scv[n*96 + kk*3 + i] + al * (vv[m] * f);
                if (LAST) out[n*160 + 64 + kk*3 + i] = val;
                else      g_v1[n*96 + kk*3 + i] = val;
            }
        }
    }
}

// ---------------- launch ----------------
static constexpr int NP_SMEM(int OS) { return (64*65 + 3*64*33 + 64*(64+OS) + 32*64 + 64) * 4; }
static constexpr int NF_SMEM(int OS) { return (64*97*2 + 96*OS + 96*32 + 96 + 64*3) * 4; }
static constexpr int EDGE_SMEM = (640 + 640 + 4096 + 64*192) * 4;

extern "C" void kernel_launch(void* const* d_in, const int* in_sizes, int n_in,
                              void* d_out, int out_size)
{
    const float* node_s = (const float*)d_in[0];
    const float* node_v = (const float*)d_in[1];
    const float* attr   = (const float*)d_in[2];
    const int*   src    = (const int*)d_in[3];
    const int*   dst    = (const int*)d_in[4];
    const float* sh     = (const float*)d_in[5];
    const float* esc    = (const float*)d_in[6];
    const float* p[18];
    for (int i = 0; i < 18; i++) p[i] = (const float*)d_in[7 + i];
    int N = in_sizes[0] / 64;
    int E = in_sizes[3];
    float* out = (float*)d_out;

    cudaFuncSetAttribute(k_nodeprep<96,false>, cudaFuncAttributeMaxDynamicSharedMemorySize, NP_SMEM(96));
    cudaFuncSetAttribute(k_nodeprep<64,true>,  cudaFuncAttributeMaxDynamicSharedMemorySize, NP_SMEM(64));
    cudaFuncSetAttribute(k_edge,               cudaFuncAttributeMaxDynamicSharedMemorySize, EDGE_SMEM);
    cudaFuncSetAttribute(k_nodefinal<96,false>,cudaFuncAttributeMaxDynamicSharedMemorySize, NF_SMEM(96));
    cudaFuncSetAttribute(k_nodefinal<64,true>, cudaFuncAttributeMaxDynamicSharedMemorySize, NF_SMEM(64));

    int nb_nodes = (N + 63) / 64;
    int nb_edges = (E + 63) / 64;

    k_zero<<<512, 256>>>(N, 1);
    k_deg<<<(E + 255) / 256, 256>>>(dst, E);

    // ---- layer 1 ----
    k_nodeprep<96,false><<<nb_nodes, 256, NP_SMEM(96)>>>(node_s, node_v, attr,
                                                         p[2], p[3], p[0], p[1], N);
    k_edge<<<nb_edges, 384, EDGE_SMEM>>>(esc, sh, src, dst, p[4], p[5], E);
    k_nodefinal<96,false><<<nb_nodes, 256, NF_SMEM(96)>>>(attr, p[6], p[7], p[8], nullptr, N);

    // ---- layer 2 ----
    k_zero<<<512, 256>>>(N, 0);
    k_nodeprep<64,true><<<nb_nodes, 256, NP_SMEM(64)>>>(nullptr, nullptr, attr,
                                                        p[11], p[12], p[9], p[10], N);
    k_edge<<<nb_edges, 384, EDGE_SMEM>>>(esc, sh, src, dst, p[13], p[14], E);
    k_nodefinal<64,true><<<nb_nodes, 256, NF_SMEM(64)>>>(attr, p[15], p[16], p[17], out, N);
}